// round 1
// baseline (speedup 1.0000x reference)
#include <cuda_runtime.h>

// FilterBankConstructorND: per-sphere Householder rotation + filter banks.
// Inputs (metadata order):
//   d_in[0]: spheres         (K, 5)  float32, K = 1048576
//   d_in[1]: ones_vec        (3,)    float32
//   d_in[2]: tetra_rotations (4,3,3) float32
// Output: concat of rotations_0 (K,3,3) then filter_banks (4K,5,1), float32.

#ifndef FB_EPS
#define FB_EPS 1e-12f
#endif

__global__ __launch_bounds__(256)
void fb_kernel(const float* __restrict__ spheres,
               const float* __restrict__ ones_vec,
               const float* __restrict__ tetra,
               float* __restrict__ out_rot,   // (K,3,3)
               float* __restrict__ out_fb,    // (4K,5) contiguous, 20 floats per k
               int K)
{
    int k = blockIdx.x * blockDim.x + threadIdx.x;
    if (k >= K) return;

    // ---- constants (broadcast loads, L1-resident) ----
    float q0 = __ldg(ones_vec + 0);
    float q1 = __ldg(ones_vec + 1);
    float q2 = __ldg(ones_vec + 2);
    {
        float qn = rsqrtf(q0 * q0 + q1 * q1 + q2 * q2);
        q0 *= qn; q1 *= qn; q2 *= qn;
    }

    // ---- load sphere row ----
    const float* s = spheres + 5 * (size_t)k;
    float s0 = __ldg(s + 0), s1 = __ldg(s + 1), s2 = __ldg(s + 2);
    float s3 = __ldg(s + 3), s4 = __ldg(s + 4);

    // centers = s[:3] / (s[4] + eps); normalize
    float inv = __frcp_rn(s4 + FB_EPS);
    float c0 = s0 * inv, c1 = s1 * inv, c2 = s2 * inv;
    float cn = rsqrtf(c0 * c0 + c1 * c1 + c2 * c2);
    float p0 = c0 * cn, p1 = c1 * cn, p2 = c2 * cn;

    // u = p + q  (first reflection axis)
    float u0 = p0 + q0, u1 = p1 + q1, u2 = p2 + q2;
    float uu = u0 * u0 + u1 * u1 + u2 * u2;
    float two_iuu = 2.0f / uu;
    float qq = q0 * q0 + q1 * q1 + q2 * q2;   // ~1, mirror reference arithmetic
    float two_iqq = 2.0f / qq;

    // H_q = I - (2/qq) q q^T
    float Hq00 = 1.0f - two_iqq * q0 * q0;
    float Hq01 =       -two_iqq * q0 * q1;
    float Hq02 =       -two_iqq * q0 * q2;
    float Hq11 = 1.0f - two_iqq * q1 * q1;
    float Hq12 =       -two_iqq * q1 * q2;
    float Hq22 = 1.0f - two_iqq * q2 * q2;

    // h = H_q u
    float qu = q0 * u0 + q1 * u1 + q2 * u2;
    float h0 = u0 - two_iqq * q0 * qu;
    float h1 = u1 - two_iqq * q1 * qu;
    float h2 = u2 - two_iqq * q2 * qu;

    // R0 = H_q H_u = H_q - (2/uu) (H_q u) u^T
    float R00 = Hq00 - two_iuu * h0 * u0;
    float R01 = Hq01 - two_iuu * h0 * u1;
    float R02 = Hq02 - two_iuu * h0 * u2;
    float R10 = Hq01 - two_iuu * h1 * u0;
    float R11 = Hq11 - two_iuu * h1 * u1;
    float R12 = Hq12 - two_iuu * h1 * u2;
    float R20 = Hq02 - two_iuu * h2 * u0;
    float R21 = Hq12 - two_iuu * h2 * u1;
    float R22 = Hq22 - two_iuu * h2 * u2;

    // ---- write rotations_0 (9 scalar stores, fully coalesced byte coverage) ----
    float* ro = out_rot + 9 * (size_t)k;
    ro[0] = R00; ro[1] = R01; ro[2] = R02;
    ro[3] = R10; ro[4] = R11; ro[5] = R12;
    ro[6] = R20; ro[7] = R21; ro[8] = R22;

    // rotated top = R0 @ s[:3]
    float t0 = R00 * s0 + R01 * s1 + R02 * s2;
    float t1 = R10 * s0 + R11 * s1 + R12 * s2;
    float t2 = R20 * s0 + R21 * s1 + R22 * s2;

    // fb_m = R0^T (T_m @ t), m = 0..3
    float f[4][3];
#pragma unroll
    for (int m = 0; m < 4; m++) {
        const float* T = tetra + 9 * m;
        float T00 = __ldg(T + 0), T01 = __ldg(T + 1), T02 = __ldg(T + 2);
        float T10 = __ldg(T + 3), T11 = __ldg(T + 4), T12 = __ldg(T + 5);
        float T20 = __ldg(T + 6), T21 = __ldg(T + 7), T22 = __ldg(T + 8);
        float w0 = T00 * t0 + T01 * t1 + T02 * t2;
        float w1 = T10 * t0 + T11 * t1 + T12 * t2;
        float w2 = T20 * t0 + T21 * t1 + T22 * t2;
        f[m][0] = R00 * w0 + R10 * w1 + R20 * w2;
        f[m][1] = R01 * w0 + R11 * w1 + R21 * w2;
        f[m][2] = R02 * w0 + R12 * w1 + R22 * w2;
    }

    // ---- write filter banks: 20 contiguous floats per k, 5x STG.128 ----
    float4* fo = reinterpret_cast<float4*>(out_fb + 20 * (size_t)k);
    fo[0] = make_float4(f[0][0], f[0][1], f[0][2], s3);
    fo[1] = make_float4(s4,      f[1][0], f[1][1], f[1][2]);
    fo[2] = make_float4(s3,      s4,      f[2][0], f[2][1]);
    fo[3] = make_float4(f[2][2], s3,      s4,      f[3][0]);
    fo[4] = make_float4(f[3][1], f[3][2], s3,      s4);
}

extern "C" void kernel_launch(void* const* d_in, const int* in_sizes, int n_in,
                              void* d_out, int out_size)
{
    const float* spheres = (const float*)d_in[0];
    const float* ones_v  = (const float*)d_in[1];
    const float* tetra   = (const float*)d_in[2];

    int K = in_sizes[0] / 5;              // spheres is (K, 5)
    float* out_rot = (float*)d_out;       // (K, 3, 3)
    float* out_fb  = out_rot + 9 * (size_t)K;  // (4K, 5)

    int threads = 256;
    int blocks  = (K + threads - 1) / threads;
    fb_kernel<<<blocks, threads>>>(spheres, ones_v, tetra, out_rot, out_fb, K);
}

// round 2
// speedup vs baseline: 1.3591x; 1.3591x over previous
#include <cuda_runtime.h>

// FilterBankConstructorND: per-sphere Householder rotation + filter banks.
// Inputs (metadata order):
//   d_in[0]: spheres         (K, 5)  float32, K = 1048576
//   d_in[1]: ones_vec        (3,)    float32
//   d_in[2]: tetra_rotations (4,3,3) float32
// Output: concat of rotations_0 (K,3,3) then filter_banks (4K,5,1), float32.
//
// R1: smem staging so all global loads/stores are fully coalesced
// (previous version was L1-wavefront bound: strided scalar accesses).

#ifndef FB_EPS
#define FB_EPS 1e-12f
#endif

#define BLK 256
#define FB_STRIDE 21   // padded (21 coprime with 32 -> conflict-free STS)

__global__ __launch_bounds__(BLK)
void fb_kernel(const float* __restrict__ spheres,
               const float* __restrict__ ones_vec,
               const float* __restrict__ tetra,
               float* __restrict__ out_rot,   // (K,3,3)
               float* __restrict__ out_fb,    // (4K,5) = 20 floats per sphere
               int K)
{
    __shared__ float s_in[5 * BLK];          //  5120 B
    __shared__ float s_rot[9 * BLK];         //  9216 B
    __shared__ float s_fb[FB_STRIDE * BLK];  // 21504 B

    const int tid = threadIdx.x;
    const size_t base = (size_t)blockIdx.x * BLK;   // first sphere of this block

    // ---- coalesced block load: 256 spheres x 5 floats ----
    const float* gin = spheres + base * 5;
#pragma unroll
    for (int i = 0; i < 5; i++)
        s_in[tid + i * BLK] = gin[tid + i * BLK];
    __syncthreads();

    // ---- per-thread compute (identical arithmetic to R0 kernel) ----
    float q0 = __ldg(ones_vec + 0);
    float q1 = __ldg(ones_vec + 1);
    float q2 = __ldg(ones_vec + 2);
    {
        float qn = rsqrtf(q0 * q0 + q1 * q1 + q2 * q2);
        q0 *= qn; q1 *= qn; q2 *= qn;
    }

    const float s0 = s_in[tid * 5 + 0];
    const float s1 = s_in[tid * 5 + 1];
    const float s2 = s_in[tid * 5 + 2];
    const float s3 = s_in[tid * 5 + 3];
    const float s4 = s_in[tid * 5 + 4];

    // centers = s[:3] / (s[4] + eps); normalize
    float inv = __frcp_rn(s4 + FB_EPS);
    float c0 = s0 * inv, c1 = s1 * inv, c2 = s2 * inv;
    float cn = rsqrtf(c0 * c0 + c1 * c1 + c2 * c2);
    float p0 = c0 * cn, p1 = c1 * cn, p2 = c2 * cn;

    // u = p + q
    float u0 = p0 + q0, u1 = p1 + q1, u2 = p2 + q2;
    float uu = u0 * u0 + u1 * u1 + u2 * u2;
    float two_iuu = 2.0f / uu;
    float qq = q0 * q0 + q1 * q1 + q2 * q2;   // ~1, mirror reference arithmetic
    float two_iqq = 2.0f / qq;

    // H_q = I - (2/qq) q q^T
    float Hq00 = 1.0f - two_iqq * q0 * q0;
    float Hq01 =       -two_iqq * q0 * q1;
    float Hq02 =       -two_iqq * q0 * q2;
    float Hq11 = 1.0f - two_iqq * q1 * q1;
    float Hq12 =       -two_iqq * q1 * q2;
    float Hq22 = 1.0f - two_iqq * q2 * q2;

    // h = H_q u
    float qu = q0 * u0 + q1 * u1 + q2 * u2;
    float h0 = u0 - two_iqq * q0 * qu;
    float h1 = u1 - two_iqq * q1 * qu;
    float h2 = u2 - two_iqq * q2 * qu;

    // R0 = H_q - (2/uu) (H_q u) u^T
    float R00 = Hq00 - two_iuu * h0 * u0;
    float R01 = Hq01 - two_iuu * h0 * u1;
    float R02 = Hq02 - two_iuu * h0 * u2;
    float R10 = Hq01 - two_iuu * h1 * u0;
    float R11 = Hq11 - two_iuu * h1 * u1;
    float R12 = Hq12 - two_iuu * h1 * u2;
    float R20 = Hq02 - two_iuu * h2 * u0;
    float R21 = Hq12 - two_iuu * h2 * u1;
    float R22 = Hq22 - two_iuu * h2 * u2;

    // stage rotations (stride 9, conflict-free)
    {
        float* r = s_rot + tid * 9;
        r[0] = R00; r[1] = R01; r[2] = R02;
        r[3] = R10; r[4] = R11; r[5] = R12;
        r[6] = R20; r[7] = R21; r[8] = R22;
    }

    // rotated top = R0 @ s[:3]
    float t0 = R00 * s0 + R01 * s1 + R02 * s2;
    float t1 = R10 * s0 + R11 * s1 + R12 * s2;
    float t2 = R20 * s0 + R21 * s1 + R22 * s2;

    // fb_m = R0^T (T_m @ t), staged at padded stride 21
    {
        float* fb = s_fb + tid * FB_STRIDE;
#pragma unroll
        for (int m = 0; m < 4; m++) {
            const float* T = tetra + 9 * m;
            float T00 = __ldg(T + 0), T01 = __ldg(T + 1), T02 = __ldg(T + 2);
            float T10 = __ldg(T + 3), T11 = __ldg(T + 4), T12 = __ldg(T + 5);
            float T20 = __ldg(T + 6), T21 = __ldg(T + 7), T22 = __ldg(T + 8);
            float w0 = T00 * t0 + T01 * t1 + T02 * t2;
            float w1 = T10 * t0 + T11 * t1 + T12 * t2;
            float w2 = T20 * t0 + T21 * t1 + T22 * t2;
            fb[m * 5 + 0] = R00 * w0 + R10 * w1 + R20 * w2;
            fb[m * 5 + 1] = R01 * w0 + R11 * w1 + R21 * w2;
            fb[m * 5 + 2] = R02 * w0 + R12 * w1 + R22 * w2;
            fb[m * 5 + 3] = s3;
            fb[m * 5 + 4] = s4;
        }
    }
    __syncthreads();

    // ---- coalesced writeback: rotations as float4 (2304 floats = 576 float4) ----
    {
        float4* ro4 = reinterpret_cast<float4*>(out_rot + base * 9);
        const float4* sr4 = reinterpret_cast<const float4*>(s_rot);
        ro4[tid]        = sr4[tid];
        ro4[tid + BLK]  = sr4[tid + BLK];
        if (tid < 576 - 2 * BLK)
            ro4[tid + 2 * BLK] = sr4[tid + 2 * BLK];
    }

    // ---- coalesced writeback: filter banks, 20 scalar passes ----
    {
        float* fo = out_fb + base * 20;
#pragma unroll
        for (int i = 0; i < 20; i++) {
            int j = tid + i * BLK;
            fo[j] = s_fb[(j / 20) * FB_STRIDE + (j % 20)];
        }
    }
}

extern "C" void kernel_launch(void* const* d_in, const int* in_sizes, int n_in,
                              void* d_out, int out_size)
{
    const float* spheres = (const float*)d_in[0];
    const float* ones_v  = (const float*)d_in[1];
    const float* tetra   = (const float*)d_in[2];

    int K = in_sizes[0] / 5;                   // spheres is (K, 5)
    float* out_rot = (float*)d_out;            // (K, 3, 3)
    float* out_fb  = out_rot + 9 * (size_t)K;  // (4K, 5)

    int blocks = K / BLK;                      // K = 2^20, exact multiple
    fb_kernel<<<blocks, BLK>>>(spheres, ones_v, tetra, out_rot, out_fb, K);
}

// round 4
// speedup vs baseline: 1.7651x; 1.2987x over previous
#include <cuda_runtime.h>
#include <cstdint>

// FilterBankConstructorND — R2: stage outputs in smem in output-linear layout,
// write to global via TMA bulk stores (cp.async.bulk), eliminating the
// LDS-readback + STG half of the l1tex traffic that bound R1.
//
// Inputs (metadata order):
//   d_in[0]: spheres         (K, 5)  float32, K = 1048576
//   d_in[1]: ones_vec        (3,)    float32
//   d_in[2]: tetra_rotations (4,3,3) float32
// Output: concat of rotations_0 (K,3,3) then filter_banks (4K,5,1), float32.

#ifndef FB_EPS
#define FB_EPS 1e-12f
#endif

#define BLK 256

__device__ __forceinline__ unsigned smem_u32(const void* p) {
    return (unsigned)__cvta_generic_to_shared(p);
}

__global__ __launch_bounds__(BLK)
void fb_kernel(const float* __restrict__ spheres,
               const float* __restrict__ ones_vec,
               const float* __restrict__ tetra,
               float* __restrict__ out_rot,   // (K,3,3)
               float* __restrict__ out_fb,    // (4K,5) = 20 floats per sphere
               int K)
{
    __shared__ __align__(128) float s_in[5 * BLK];    //  5120 B
    __shared__ __align__(128) float s_rot[9 * BLK];   //  9216 B, output-linear
    __shared__ __align__(128) float s_fb[20 * BLK];   // 20480 B, output-linear

    const int tid = threadIdx.x;
    const size_t base = (size_t)blockIdx.x * BLK;   // first sphere of this block

    // ---- coalesced block load: 256 spheres x 5 floats ----
    const float* gin = spheres + base * 5;
#pragma unroll
    for (int i = 0; i < 5; i++)
        s_in[tid + i * BLK] = gin[tid + i * BLK];
    __syncthreads();

    // ---- constants ----
    float q0 = __ldg(ones_vec + 0);
    float q1 = __ldg(ones_vec + 1);
    float q2 = __ldg(ones_vec + 2);
    {
        float qn = rsqrtf(q0 * q0 + q1 * q1 + q2 * q2);
        q0 *= qn; q1 *= qn; q2 *= qn;
    }

    const float s0 = s_in[tid * 5 + 0];
    const float s1 = s_in[tid * 5 + 1];
    const float s2 = s_in[tid * 5 + 2];
    const float s3 = s_in[tid * 5 + 3];
    const float s4 = s_in[tid * 5 + 4];

    // centers = s[:3] / (s[4] + eps); normalize
    float inv = __frcp_rn(s4 + FB_EPS);
    float c0 = s0 * inv, c1 = s1 * inv, c2 = s2 * inv;
    float cn = rsqrtf(c0 * c0 + c1 * c1 + c2 * c2);
    float p0 = c0 * cn, p1 = c1 * cn, p2 = c2 * cn;

    // u = p + q
    float u0 = p0 + q0, u1 = p1 + q1, u2 = p2 + q2;
    float uu = u0 * u0 + u1 * u1 + u2 * u2;
    float two_iuu = 2.0f / uu;
    float qq = q0 * q0 + q1 * q1 + q2 * q2;   // ~1, mirror reference arithmetic
    float two_iqq = 2.0f / qq;

    // H_q = I - (2/qq) q q^T
    float Hq00 = 1.0f - two_iqq * q0 * q0;
    float Hq01 =       -two_iqq * q0 * q1;
    float Hq02 =       -two_iqq * q0 * q2;
    float Hq11 = 1.0f - two_iqq * q1 * q1;
    float Hq12 =       -two_iqq * q1 * q2;
    float Hq22 = 1.0f - two_iqq * q2 * q2;

    // h = H_q u
    float qu = q0 * u0 + q1 * u1 + q2 * u2;
    float h0 = u0 - two_iqq * q0 * qu;
    float h1 = u1 - two_iqq * q1 * qu;
    float h2 = u2 - two_iqq * q2 * qu;

    // R0 = H_q - (2/uu) (H_q u) u^T
    float R00 = Hq00 - two_iuu * h0 * u0;
    float R01 = Hq01 - two_iuu * h0 * u1;
    float R02 = Hq02 - two_iuu * h0 * u2;
    float R10 = Hq01 - two_iuu * h1 * u0;
    float R11 = Hq11 - two_iuu * h1 * u1;
    float R12 = Hq12 - two_iuu * h1 * u2;
    float R20 = Hq02 - two_iuu * h2 * u0;
    float R21 = Hq12 - two_iuu * h2 * u1;
    float R22 = Hq22 - two_iuu * h2 * u2;

    // stage rotations output-linear (stride 9, conflict-free STS)
    {
        float* r = s_rot + tid * 9;
        r[0] = R00; r[1] = R01; r[2] = R02;
        r[3] = R10; r[4] = R11; r[5] = R12;
        r[6] = R20; r[7] = R21; r[8] = R22;
    }

    // rotated top = R0 @ s[:3]
    float t0 = R00 * s0 + R01 * s1 + R02 * s2;
    float t1 = R10 * s0 + R11 * s1 + R12 * s2;
    float t2 = R20 * s0 + R21 * s1 + R22 * s2;

    // fb_m = R0^T (T_m @ t); stage output-linear at stride 20 via 5x STS.128
    // (80B thread stride -> disjoint bank quads per 8-lane phase, conflict-free)
    {
        float f[4][3];
#pragma unroll
        for (int m = 0; m < 4; m++) {
            const float* T = tetra + 9 * m;
            float T00 = __ldg(T + 0), T01 = __ldg(T + 1), T02 = __ldg(T + 2);
            float T10 = __ldg(T + 3), T11 = __ldg(T + 4), T12 = __ldg(T + 5);
            float T20 = __ldg(T + 6), T21 = __ldg(T + 7), T22 = __ldg(T + 8);
            float w0 = T00 * t0 + T01 * t1 + T02 * t2;
            float w1 = T10 * t0 + T11 * t1 + T12 * t2;
            float w2 = T20 * t0 + T21 * t1 + T22 * t2;
            f[m][0] = R00 * w0 + R10 * w1 + R20 * w2;
            f[m][1] = R01 * w0 + R11 * w1 + R21 * w2;
            f[m][2] = R02 * w0 + R12 * w1 + R22 * w2;
        }
        float4* fb4 = reinterpret_cast<float4*>(s_fb + tid * 20);
        fb4[0] = make_float4(f[0][0], f[0][1], f[0][2], s3);
        fb4[1] = make_float4(s4,      f[1][0], f[1][1], f[1][2]);
        fb4[2] = make_float4(s3,      s4,      f[2][0], f[2][1]);
        fb4[3] = make_float4(f[2][2], s3,      s4,      f[3][0]);
        fb4[4] = make_float4(f[3][1], f[3][2], s3,      s4);
    }
    __syncthreads();

    // ---- TMA bulk stores: smem -> global, no LDS/STG traffic ----
    if (tid == 0) {
        asm volatile("fence.proxy.async.shared::cta;" ::: "memory");
        uint64_t g_rot = (uint64_t)(out_rot + base * 9);
        uint64_t g_fb  = (uint64_t)(out_fb  + base * 20);
        unsigned s_rot_a = smem_u32(s_rot);
        unsigned s_fb_a  = smem_u32(s_fb);
        asm volatile(
            "cp.async.bulk.global.shared::cta.bulk_group [%0], [%1], %2;"
            :: "l"(g_rot), "r"(s_rot_a), "n"(9 * BLK * 4) : "memory");
        asm volatile(
            "cp.async.bulk.global.shared::cta.bulk_group [%0], [%1], %2;"
            :: "l"(g_fb), "r"(s_fb_a), "n"(20 * BLK * 4) : "memory");
        asm volatile("cp.async.bulk.commit_group;" ::: "memory");
        asm volatile("cp.async.bulk.wait_group 0;" ::: "memory");
    }
}

extern "C" void kernel_launch(void* const* d_in, const int* in_sizes, int n_in,
                              void* d_out, int out_size)
{
    const float* spheres = (const float*)d_in[0];
    const float* ones_v  = (const float*)d_in[1];
    const float* tetra   = (const float*)d_in[2];

    int K = in_sizes[0] / 5;                   // spheres is (K, 5)
    float* out_rot = (float*)d_out;            // (K, 3, 3)
    float* out_fb  = out_rot + 9 * (size_t)K;  // (4K, 5)

    int blocks = K / BLK;                      // K = 2^20, exact multiple
    fb_kernel<<<blocks, BLK>>>(spheres, ones_v, tetra, out_rot, out_fb, K);
}